// round 9
// baseline (speedup 1.0000x reference)
#include <cuda_runtime.h>
#include <cuda_bf16.h>
#include <math.h>
#include <stdint.h>

#define N_Bc  4
#define N_T   1024
#define N_D   768
#define N_H   12
#define N_L   6
#define N_DF  3072
#define N_V   32000
#define N_BT  (N_Bc*N_T)
#define N_QKV (3*N_D)

// ============================ PTX helpers ============================
__device__ __forceinline__ uint32_t smem_u32(const void* p){
    uint32_t a;
    asm("{ .reg .u64 t; cvta.to.shared.u64 t, %1; cvt.u32.u64 %0, t; }" : "=r"(a) : "l"(p));
    return a;
}
__device__ __forceinline__ void ldsm_x4(uint32_t* r, uint32_t addr){
    asm volatile("ldmatrix.sync.aligned.m8n8.x4.shared.b16 {%0,%1,%2,%3}, [%4];"
      : "=r"(r[0]),"=r"(r[1]),"=r"(r[2]),"=r"(r[3]) : "r"(addr));
}
__device__ __forceinline__ void ldsm_x2(uint32_t* r, uint32_t addr){
    asm volatile("ldmatrix.sync.aligned.m8n8.x2.shared.b16 {%0,%1}, [%2];"
      : "=r"(r[0]),"=r"(r[1]) : "r"(addr));
}
__device__ __forceinline__ void mma_bf16(float* c, const uint32_t* a, const uint32_t* b){
    asm volatile("mma.sync.aligned.m16n8k16.row.col.f32.bf16.bf16.f32 "
        "{%0,%1,%2,%3}, {%4,%5,%6,%7}, {%8,%9}, {%0,%1,%2,%3};"
        : "+f"(c[0]), "+f"(c[1]), "+f"(c[2]), "+f"(c[3])
        : "r"(a[0]), "r"(a[1]), "r"(a[2]), "r"(a[3]), "r"(b[0]), "r"(b[1]));
}
__device__ __forceinline__ void cp16(uint32_t dst, const void* src){
    asm volatile("cp.async.cg.shared.global [%0], [%1], 16;" :: "r"(dst), "l"(src));
}
#define CP_COMMIT() asm volatile("cp.async.commit_group;" ::: "memory")
#define CP_WAIT1()  asm volatile("cp.async.wait_group 1;" ::: "memory")
#define CP_WAIT0()  asm volatile("cp.async.wait_group 0;" ::: "memory")

// bf16 split helpers
__device__ __forceinline__ void split2(float v, __nv_bfloat16& h, __nv_bfloat16& l){
    h = __float2bfloat16(v);
    l = __float2bfloat16(v - __bfloat162float(h));
}

// ============================ scratch (device globals) ============================
__device__ float g_x  [N_BT*N_D];
__device__ float g_qkv[N_BT*N_QKV];
__device__ __nv_bfloat16 g_hh [N_BT*N_D],  g_hl [N_BT*N_D];    // LN out / attn out (A operand)
__device__ __nv_bfloat16 g_ffh[N_BT*N_DF], g_ffl[N_BT*N_DF];   // GELU out (A operand)

// transposed + split weights: [N, K] row-major bf16 (hi, lo)
__device__ __nv_bfloat16 g_wqkv_h[N_L*N_QKV*N_D], g_wqkv_l[N_L*N_QKV*N_D];
__device__ __nv_bfloat16 g_wo_h  [N_L*N_D*N_D],   g_wo_l  [N_L*N_D*N_D];
__device__ __nv_bfloat16 g_w1_h  [N_L*N_DF*N_D],  g_w1_l  [N_L*N_DF*N_D];
__device__ __nv_bfloat16 g_w2_h  [N_L*N_D*N_DF],  g_w2_l  [N_L*N_D*N_DF];
__device__ __nv_bfloat16 g_hd_h  [(size_t)N_V*N_D], g_hd_l [(size_t)N_V*N_D];

// ============================ weight convert (transpose + bf16 split) ============================
// src W [K, N] f32 -> out [N, K] bf16 hi/lo. 64k x 32n tile, 16B coalesced stores.
__global__ __launch_bounds__(256) void convw_kernel(const float* __restrict__ W,
                                                    __nv_bfloat16* __restrict__ oh,
                                                    __nv_bfloat16* __restrict__ ol,
                                                    int K, int N){
    __shared__ float t[64][33];
    const int n0 = blockIdx.x*32, k0 = blockIdx.y*64;
    const int tx = threadIdx.x & 31, ty = threadIdx.x >> 5;
    #pragma unroll
    for(int r = ty; r < 64; r += 8)
        t[r][tx] = W[(size_t)(k0+r)*N + n0 + tx];
    __syncthreads();
    const int n = threadIdx.x >> 3, k8 = (threadIdx.x & 7)*8;
    ushort hh[8], ll[8];
    #pragma unroll
    for(int j=0;j<8;j++){
        float v = t[k8+j][n];
        __nv_bfloat16 h, l; split2(v, h, l);
        hh[j] = __bfloat16_as_ushort(h);
        ll[j] = __bfloat16_as_ushort(l);
    }
    size_t o = (size_t)(n0+n)*K + k0 + k8;
    *(uint4*)(oh + o) = *(uint4*)hh;
    *(uint4*)(ol + o) = *(uint4*)ll;
}

// ============================ embedding ============================
__global__ __launch_bounds__(256) void embed_kernel(const int* __restrict__ idx,
                                                    const float* __restrict__ tok,
                                                    const float* __restrict__ pos){
    int bt = blockIdx.x;
    int t  = bt & (N_T-1);
    int token = idx[bt];
    const float* tp = tok + (size_t)token*N_D;
    const float* pp = pos + (size_t)t*N_D;
    float* xp = g_x + (size_t)bt*N_D;
    for(int d = threadIdx.x; d < N_D; d += 256)
        xp[d] = tp[d] + pp[d];
}

// ============================ layernorm -> split bf16 ============================
__global__ __launch_bounds__(256) void ln_kernel(const float* __restrict__ in,
                                                 __nv_bfloat16* __restrict__ outh,
                                                 __nv_bfloat16* __restrict__ outl,
                                                 const float* __restrict__ gam,
                                                 const float* __restrict__ bet){
    int row = blockIdx.x;
    int tid = threadIdx.x;
    const float* xr = in + (size_t)row*N_D;
    float v0 = xr[tid], v1 = xr[tid+256], v2 = xr[tid+512];
    __shared__ float red[8];
    float s = v0+v1+v2;
    #pragma unroll
    for(int o=16;o>0;o>>=1) s += __shfl_xor_sync(0xffffffffu, s, o);
    if((tid&31)==0) red[tid>>5] = s;
    __syncthreads();
    float tot = 0.f;
    #pragma unroll
    for(int w=0;w<8;w++) tot += red[w];
    float mu = tot * (1.f/N_D);
    float d0=v0-mu, d1=v1-mu, d2=v2-mu;
    float s2 = d0*d0 + d1*d1 + d2*d2;
    #pragma unroll
    for(int o=16;o>0;o>>=1) s2 += __shfl_xor_sync(0xffffffffu, s2, o);
    __syncthreads();
    if((tid&31)==0) red[tid>>5] = s2;
    __syncthreads();
    float tot2 = 0.f;
    #pragma unroll
    for(int w=0;w<8;w++) tot2 += red[w];
    float rstd = rsqrtf(tot2*(1.f/N_D) + 1e-5f);
    __nv_bfloat16* oh = outh + (size_t)row*N_D;
    __nv_bfloat16* ol = outl + (size_t)row*N_D;
    float y0 = d0*rstd*gam[tid]     + bet[tid];
    float y1 = d1*rstd*gam[tid+256] + bet[tid+256];
    float y2 = d2*rstd*gam[tid+512] + bet[tid+512];
    split2(y0, oh[tid],     ol[tid]);
    split2(y1, oh[tid+256], ol[tid+256]);
    split2(y2, oh[tid+512], ol[tid+512]);
}

// ============================ mma.sync split-bf16 GEMM ============================
// C[M,N] = A[M,K] @ W[K,N]; A given split (Ah,Al [M,K]), W split+transposed (Bh,Bl [N,K]).
// CTA 128x128x32, 8 warps of 64x32, 3-stage cp.async ring, pure ldsm+mma hot loop.
// D = Ah*Bh + Ah*Bl + Al*Bh  (fp32 accumulate).
// EPI: 0 none, 1 +bias, 2 +bias+residual, 3 +bias then exact GELU.
// SPLIT_OUT: write Ch/Cl bf16 pair instead of f32 C.
#define BM 128
#define BN 128
#define BK 32
#define SA 40                      // smem stride in halfs (32 + 8 pad)
#define TILE_B (BM*SA*2)           // 10240
#define OFF_AH 0
#define OFF_AL (1*TILE_B)
#define OFF_BH (2*TILE_B)
#define OFF_BL (3*TILE_B)
#define STAGE_BYTES (4*TILE_B)     // 40960
#define NSTG 3
#define GEMM_SMEM (NSTG*STAGE_BYTES)  // 122880

template<int EPI, int SPLIT_OUT>
__global__ void __launch_bounds__(256) gemm_mma(
        const __nv_bfloat16* __restrict__ Ah, const __nv_bfloat16* __restrict__ Al,
        const __nv_bfloat16* __restrict__ Bh, const __nv_bfloat16* __restrict__ Bl,
        const float* __restrict__ bias, const float* __restrict__ res,
        float* __restrict__ C,
        __nv_bfloat16* __restrict__ Ch, __nv_bfloat16* __restrict__ Cl,
        int M, int N, int K){
    extern __shared__ char sm[];
    const uint32_t sb = smem_u32(sm);
    const int tid = threadIdx.x, wid = tid>>5, lane = tid&31;
    const int mBase = blockIdx.x*BM, nBase = blockIdx.y*BN;
    const int wm = (wid>>2)*64, wn = (wid&3)*32;

    const __nv_bfloat16* Ahp = Ah + (size_t)mBase*K;
    const __nv_bfloat16* Alp = Al + (size_t)mBase*K;
    const __nv_bfloat16* Bhp = Bh + (size_t)nBase*K;
    const __nv_bfloat16* Blp = Bl + (size_t)nBase*K;
    const int nk = K / BK;

    float c[4][4][4];
    #pragma unroll
    for(int mt=0;mt<4;mt++)
        #pragma unroll
        for(int nt=0;nt<4;nt++)
            #pragma unroll
            for(int r=0;r<4;r++) c[mt][nt][r] = 0.f;

    // prefetch: both A (128 rows) and B (128 rows), 4x16B per row per split
    auto prefetch = [&](int k0, int s){
        uint32_t base = sb + s*STAGE_BYTES;
        #pragma unroll
        for(int i=0;i<2;i++){
            int v = tid + i*256;
            int row = v >> 2, seg = (v & 3)*8;
            uint32_t off = (uint32_t)((row*SA + seg)*2);
            cp16(base + OFF_AH + off, Ahp + (size_t)row*K + k0 + seg);
            cp16(base + OFF_AL + off, Alp + (size_t)row*K + k0 + seg);
            cp16(base + OFF_BH + off, Bhp + (size_t)row*K + k0 + seg);
            cp16(base + OFF_BL + off, Blp + (size_t)row*K + k0 + seg);
        }
    };

    auto compute = [&](uint32_t stg){
        #pragma unroll
        for(int ks=0;ks<2;ks++){
            uint32_t ah[4][4], al[4][4], bh[4][2], bl[4][2];
            const uint32_t a_lo = (uint32_t)(((lane&15)*SA + ks*16 + (lane>>4)*8)*2);
            #pragma unroll
            for(int mt=0;mt<4;mt++){
                uint32_t a = stg + (uint32_t)(((wm + mt*16)*SA)*2) + a_lo;
                ldsm_x4(ah[mt], a + OFF_AH);
                ldsm_x4(al[mt], a + OFF_AL);
            }
            const uint32_t b_lo = (uint32_t)(((lane&7)*SA + ks*16 + ((lane>>3)&1)*8)*2);
            #pragma unroll
            for(int nt=0;nt<4;nt++){
                uint32_t b = stg + (uint32_t)(((wn + nt*8)*SA)*2) + b_lo;
                ldsm_x2(bh[nt], b + OFF_BH);
                ldsm_x2(bl[nt], b + OFF_BL);
            }
            #pragma unroll
            for(int mt=0;mt<4;mt++)
                #pragma unroll
                for(int nt=0;nt<4;nt++){
                    mma_bf16(c[mt][nt], ah[mt], bh[nt]);
                    mma_bf16(c[mt][nt], ah[mt], bl[nt]);
                    mma_bf16(c[mt][nt], al[mt], bh[nt]);
                }
        }
    };

    // prologue: stages 0,1 in flight (nk >= 24 always here)
    prefetch(0, 0);    CP_COMMIT();
    prefetch(BK, 1);   CP_COMMIT();

    for(int i=0;i<nk;i++){
        if(i < nk-1) CP_WAIT1(); else CP_WAIT0();
        __syncthreads();
        if(i+2 < nk){ prefetch((i+2)*BK, (i+2)%NSTG); CP_COMMIT(); }
        compute(sb + (i%NSTG)*STAGE_BYTES);
    }

    // ---- epilogue ----
    const int g = lane>>2, t2 = (lane&3)*2;
    #pragma unroll
    for(int mt=0;mt<4;mt++){
        const int row0 = mBase + wm + mt*16 + g;
        #pragma unroll
        for(int nt=0;nt<4;nt++){
            const int col = nBase + wn + nt*8 + t2;
            float v[4] = { c[mt][nt][0], c[mt][nt][1], c[mt][nt][2], c[mt][nt][3] };
            if(EPI != 0){
                float2 b2 = *(const float2*)(bias + col);
                v[0]+=b2.x; v[1]+=b2.y; v[2]+=b2.x; v[3]+=b2.y;
            }
            if(EPI == 2){
                float2 r0 = *(const float2*)(res + (size_t)row0*N + col);
                float2 r1 = *(const float2*)(res + (size_t)(row0+8)*N + col);
                v[0]+=r0.x; v[1]+=r0.y; v[2]+=r1.x; v[3]+=r1.y;
            }
            if(EPI == 3){
                #pragma unroll
                for(int r=0;r<4;r++) v[r] = 0.5f*v[r]*(1.f + erff(v[r]*0.70710678118654752f));
            }
            if(SPLIT_OUT){
                __nv_bfloat16 h0,l0,h1,l1,h2,l2,h3,l3;
                split2(v[0],h0,l0); split2(v[1],h1,l1);
                split2(v[2],h2,l2); split2(v[3],h3,l3);
                ushort2 ph0 = make_ushort2(__bfloat16_as_ushort(h0), __bfloat16_as_ushort(h1));
                ushort2 pl0 = make_ushort2(__bfloat16_as_ushort(l0), __bfloat16_as_ushort(l1));
                ushort2 ph1 = make_ushort2(__bfloat16_as_ushort(h2), __bfloat16_as_ushort(h3));
                ushort2 pl1 = make_ushort2(__bfloat16_as_ushort(l2), __bfloat16_as_ushort(l3));
                *(ushort2*)(Ch + (size_t)row0*N + col)     = ph0;
                *(ushort2*)(Cl + (size_t)row0*N + col)     = pl0;
                *(ushort2*)(Ch + (size_t)(row0+8)*N + col) = ph1;
                *(ushort2*)(Cl + (size_t)(row0+8)*N + col) = pl1;
            } else {
                *(float2*)(C + (size_t)row0*N + col)     = make_float2(v[0], v[1]);
                *(float2*)(C + (size_t)(row0+8)*N + col) = make_float2(v[2], v[3]);
            }
        }
    }
}

// ============================ fused causal flash attention (fp32 SIMT, split-bf16 out) ====
// QKV packed [B*T, 2304]: Q at col h*64, K at 768+h*64, V at 1536+h*64.
#define APAD 65
#define ATT_SMEM (3*64*APAD*4)
#define QKV_S N_QKV

__global__ __launch_bounds__(256) void attn_kernel(const float* __restrict__ QKV,
                                                   __nv_bfloat16* __restrict__ Oh,
                                                   __nv_bfloat16* __restrict__ Ol){
    extern __shared__ float smf[];
    float* Qs  = smf;
    float* KVs = smf + 64*APAD;
    float* Ps  = smf + 2*64*APAD;
    const int qtile = blockIdx.x;
    const int bh = blockIdx.y;
    const int b = bh / N_H, h = bh % N_H;
    const int tid = threadIdx.x;
    const int tr = tid >> 4, tc = tid & 15;
    const float* Qb = QKV + (size_t)b*N_T*QKV_S + h*64;
    const float* Kb = Qb + N_D;
    const float* Vb = Qb + 2*N_D;

    for(int v4 = tid; v4 < 1024; v4 += 256){
        int r = v4 >> 4, c = (v4 & 15) << 2;
        float4 f = *(const float4*)(Qb + (size_t)(qtile*64 + r)*QKV_S + c);
        float* d = Qs + r*APAD + c;
        d[0]=f.x; d[1]=f.y; d[2]=f.z; d[3]=f.w;
    }

    float m_[4], l_[4], acc[4][4];
    #pragma unroll
    for(int i=0;i<4;i++){
        m_[i] = -1e30f; l_[i] = 0.f;
        #pragma unroll
        for(int j=0;j<4;j++) acc[i][j] = 0.f;
    }

    for(int kt = 0; kt <= qtile; kt++){
        for(int v4 = tid; v4 < 1024; v4 += 256){
            int r = v4 >> 4, c = (v4 & 15) << 2;
            float4 f = *(const float4*)(Kb + (size_t)(kt*64 + r)*QKV_S + c);
            float* d = KVs + r*APAD + c;
            d[0]=f.x; d[1]=f.y; d[2]=f.z; d[3]=f.w;
        }
        __syncthreads();

        float s[4][4];
        #pragma unroll
        for(int i=0;i<4;i++)
            #pragma unroll
            for(int j=0;j<4;j++) s[i][j] = 0.f;
        #pragma unroll 8
        for(int kk=0;kk<64;kk++){
            float qa[4], ka[4];
            #pragma unroll
            for(int i=0;i<4;i++) qa[i] = Qs[(tr*4+i)*APAD + kk];
            #pragma unroll
            for(int j=0;j<4;j++) ka[j] = KVs[(tc*4+j)*APAD + kk];
            #pragma unroll
            for(int i=0;i<4;i++)
                #pragma unroll
                for(int j=0;j<4;j++) s[i][j] += qa[i]*ka[j];
        }
        const float scl = 0.125f;
        if(kt == qtile){
            #pragma unroll
            for(int i=0;i<4;i++)
                #pragma unroll
                for(int j=0;j<4;j++)
                    s[i][j] = (tc*4+j <= tr*4+i) ? s[i][j]*scl : -1e30f;
        } else {
            #pragma unroll
            for(int i=0;i<4;i++)
                #pragma unroll
                for(int j=0;j<4;j++) s[i][j] *= scl;
        }

        #pragma unroll
        for(int i=0;i<4;i++){
            float rm = fmaxf(fmaxf(s[i][0],s[i][1]), fmaxf(s[i][2],s[i][3]));
            #pragma unroll
            for(int o=8;o>0;o>>=1) rm = fmaxf(rm, __shfl_xor_sync(0xffffffffu, rm, o));
            float mn = fmaxf(m_[i], rm);
            float corr = expf(m_[i] - mn);
            m_[i] = mn;
            float rs = 0.f;
            #pragma unroll
            for(int j=0;j<4;j++){ float p = expf(s[i][j] - mn); s[i][j] = p; rs += p; }
            #pragma unroll
            for(int o=8;o>0;o>>=1) rs += __shfl_xor_sync(0xffffffffu, rs, o);
            l_[i] = l_[i]*corr + rs;
            #pragma unroll
            for(int j=0;j<4;j++){ acc[i][j] *= corr; Ps[(tr*4+i)*APAD + tc*4+j] = s[i][j]; }
        }
        __syncthreads();

        for(int v4 = tid; v4 < 1024; v4 += 256){
            int r = v4 >> 4, c = (v4 & 15) << 2;
            float4 f = *(const float4*)(Vb + (size_t)(kt*64 + r)*QKV_S + c);
            float* d = KVs + r*APAD + c;
            d[0]=f.x; d[1]=f.y; d[2]=f.z; d[3]=f.w;
        }
        __syncthreads();

        #pragma unroll 8
        for(int kk=0;kk<64;kk++){
            float pa[4], va[4];
            #pragma unroll
            for(int i=0;i<4;i++) pa[i] = Ps[(tr*4+i)*APAD + kk];
            #pragma unroll
            for(int j=0;j<4;j++) va[j] = KVs[kk*APAD + tc*4 + j];
            #pragma unroll
            for(int i=0;i<4;i++)
                #pragma unroll
                for(int j=0;j<4;j++) acc[i][j] += pa[i]*va[j];
        }
        __syncthreads();
    }

    __nv_bfloat16* Obh = Oh + (size_t)b*N_T*N_D + h*64;
    __nv_bfloat16* Obl = Ol + (size_t)b*N_T*N_D + h*64;
    #pragma unroll
    for(int i=0;i<4;i++){
        float inv = 1.f / l_[i];
        int r = qtile*64 + tr*4 + i;
        ushort hh[4], ll[4];
        #pragma unroll
        for(int j=0;j<4;j++){
            __nv_bfloat16 h_, l_2; split2(acc[i][j]*inv, h_, l_2);
            hh[j] = __bfloat16_as_ushort(h_); ll[j] = __bfloat16_as_ushort(l_2);
        }
        *(ushort4*)(Obh + (size_t)r*N_D + tc*4) = *(ushort4*)hh;
        *(ushort4*)(Obl + (size_t)r*N_D + tc*4) = *(ushort4*)ll;
    }
}

// ============================ host orchestration ============================
extern "C" void kernel_launch(void* const* d_in, const int* in_sizes, int n_in,
                              void* d_out, int out_size){
    const int*   idx   = (const int*)  d_in[0];
    const float* tok   = (const float*)d_in[1];
    const float* pos   = (const float*)d_in[2];
    const float* Wq    = (const float*)d_in[3];
    const float* Wk    = (const float*)d_in[4];
    const float* Wv    = (const float*)d_in[5];
    const float* Wo    = (const float*)d_in[6];
    const float* bo    = (const float*)d_in[7];
    const float* W1    = (const float*)d_in[8];
    const float* b1    = (const float*)d_in[9];
    const float* W2    = (const float*)d_in[10];
    const float* b2    = (const float*)d_in[11];
    const float* ln1g  = (const float*)d_in[12];
    const float* ln1b  = (const float*)d_in[13];
    const float* ln2g  = (const float*)d_in[14];
    const float* ln2b  = (const float*)d_in[15];
    const float* lnfg  = (const float*)d_in[16];
    const float* lnfb  = (const float*)d_in[17];
    const float* headW = (const float*)d_in[18];
    const float* headb = (const float*)d_in[19];
    float* out = (float*)d_out;

    float *x,*qkv;
    cudaGetSymbolAddress((void**)&x,   g_x);
    cudaGetSymbolAddress((void**)&qkv, g_qkv);
    __nv_bfloat16 *hh,*hl,*ffh,*ffl;
    cudaGetSymbolAddress((void**)&hh,  g_hh);
    cudaGetSymbolAddress((void**)&hl,  g_hl);
    cudaGetSymbolAddress((void**)&ffh, g_ffh);
    cudaGetSymbolAddress((void**)&ffl, g_ffl);
    __nv_bfloat16 *wqkvh,*wqkvl,*woh,*wol,*w1h,*w1l,*w2h,*w2l,*hdh,*hdl;
    cudaGetSymbolAddress((void**)&wqkvh, g_wqkv_h);
    cudaGetSymbolAddress((void**)&wqkvl, g_wqkv_l);
    cudaGetSymbolAddress((void**)&woh,   g_wo_h);
    cudaGetSymbolAddress((void**)&wol,   g_wo_l);
    cudaGetSymbolAddress((void**)&w1h,   g_w1_h);
    cudaGetSymbolAddress((void**)&w1l,   g_w1_l);
    cudaGetSymbolAddress((void**)&w2h,   g_w2_h);
    cudaGetSymbolAddress((void**)&w2l,   g_w2_l);
    cudaGetSymbolAddress((void**)&hdh,   g_hd_h);
    cudaGetSymbolAddress((void**)&hdl,   g_hd_l);

    cudaFuncSetAttribute(attn_kernel, cudaFuncAttributeMaxDynamicSharedMemorySize, ATT_SMEM);
    cudaFuncSetAttribute(gemm_mma<0,0>, cudaFuncAttributeMaxDynamicSharedMemorySize, GEMM_SMEM);
    cudaFuncSetAttribute(gemm_mma<1,0>, cudaFuncAttributeMaxDynamicSharedMemorySize, GEMM_SMEM);
    cudaFuncSetAttribute(gemm_mma<2,0>, cudaFuncAttributeMaxDynamicSharedMemorySize, GEMM_SMEM);
    cudaFuncSetAttribute(gemm_mma<3,1>, cudaFuncAttributeMaxDynamicSharedMemorySize, GEMM_SMEM);

    // ---- weight conversion: transpose to [N,K] + bf16 hi/lo split ----
    // convw grid: (N/32, K/64)
    const dim3 cDD(N_D/32,  N_D/64);    // 24 x 12
    const dim3 cW1(N_DF/32, N_D/64);    // out [3072,768]
    const dim3 cW2(N_D/32,  N_DF/64);   // out [768,3072]
    for(int l=0;l<N_L;l++){
        size_t qkvOff = (size_t)l*N_QKV*N_D;
        convw_kernel<<<cDD,256>>>(Wq + (size_t)l*N_D*N_D, wqkvh + qkvOff,                     wqkvl + qkvOff,                     N_D, N_D);
        convw_kernel<<<cDD,256>>>(Wk + (size_t)l*N_D*N_D, wqkvh + qkvOff + (size_t)N_D*N_D,   wqkvl + qkvOff + (size_t)N_D*N_D,   N_D, N_D);
        convw_kernel<<<cDD,256>>>(Wv + (size_t)l*N_D*N_D, wqkvh + qkvOff + (size_t)2*N_D*N_D, wqkvl + qkvOff + (size_t)2*N_D*N_D, N_D, N_D);
        convw_kernel<<<cDD,256>>>(Wo + (size_t)l*N_D*N_D, woh + (size_t)l*N_D*N_D, wol + (size_t)l*N_D*N_D, N_D, N_D);
        convw_kernel<<<cW1,256>>>(W1 + (size_t)l*N_D*N_DF, w1h + (size_t)l*N_DF*N_D, w1l + (size_t)l*N_DF*N_D, N_D, N_DF);
        convw_kernel<<<cW2,256>>>(W2 + (size_t)l*N_DF*N_D, w2h + (size_t)l*N_D*N_DF, w2l + (size_t)l*N_D*N_DF, N_DF, N_D);
    }
    convw_kernel<<<dim3(N_V/32, N_D/64),256>>>(headW, hdh, hdl, N_D, N_V);

    embed_kernel<<<N_BT, 256>>>(idx, tok, pos);

    const dim3 gQKV(N_BT/BM, N_QKV/BN);  // 32 x 18
    const dim3 gOUT(N_BT/BM, N_D/BN);    // 32 x 6
    const dim3 gFF1(N_BT/BM, N_DF/BN);   // 32 x 24
    const dim3 gHead(N_BT/BM, N_V/BN);   // 32 x 250
    const dim3 gAtt(N_T/64, N_Bc*N_H);   // 16 x 48

    for(int l=0;l<N_L;l++){
        ln_kernel<<<N_BT,256>>>(x, hh, hl, ln1g + l*N_D, ln1b + l*N_D);
        gemm_mma<0,0><<<gQKV,256,GEMM_SMEM>>>(hh, hl,
                wqkvh + (size_t)l*N_QKV*N_D, wqkvl + (size_t)l*N_QKV*N_D,
                nullptr, nullptr, qkv, nullptr, nullptr, N_BT, N_QKV, N_D);
        attn_kernel<<<gAtt,256,ATT_SMEM>>>(qkv, hh, hl);
        gemm_mma<2,0><<<gOUT,256,GEMM_SMEM>>>(hh, hl,
                woh + (size_t)l*N_D*N_D, wol + (size_t)l*N_D*N_D,
                bo + l*N_D, x, x, nullptr, nullptr, N_BT, N_D, N_D);
        ln_kernel<<<N_BT,256>>>(x, hh, hl, ln2g + l*N_D, ln2b + l*N_D);
        gemm_mma<3,1><<<gFF1,256,GEMM_SMEM>>>(hh, hl,
                w1h + (size_t)l*N_DF*N_D, w1l + (size_t)l*N_DF*N_D,
                b1 + l*N_DF, nullptr, nullptr, ffh, ffl, N_BT, N_DF, N_D);
        gemm_mma<2,0><<<gOUT,256,GEMM_SMEM>>>(ffh, ffl,
                w2h + (size_t)l*N_D*N_DF, w2l + (size_t)l*N_D*N_DF,
                b2 + l*N_D, x, x, nullptr, nullptr, N_BT, N_D, N_DF);
    }
    ln_kernel<<<N_BT,256>>>(x, hh, hl, lnfg, lnfb);
    gemm_mma<1,0><<<gHead,256,GEMM_SMEM>>>(hh, hl, hdh, hdl,
            headb, nullptr, out, nullptr, nullptr, N_BT, N_V, N_D);
}

// round 10
// speedup vs baseline: 1.0009x; 1.0009x over previous
#include <cuda_runtime.h>
#include <cuda_bf16.h>
#include <math.h>
#include <stdint.h>

#define N_Bc  4
#define N_T   1024
#define N_D   768
#define N_H   12
#define N_L   6
#define N_DF  3072
#define N_V   32000
#define N_BT  (N_Bc*N_T)
#define N_QKV (3*N_D)

// ============================ PTX helpers ============================
__device__ __forceinline__ uint32_t smem_u32(const void* p){
    uint32_t a;
    asm("{ .reg .u64 t; cvta.to.shared.u64 t, %1; cvt.u32.u64 %0, t; }" : "=r"(a) : "l"(p));
    return a;
}
__device__ __forceinline__ void ldsm_x4(uint32_t* r, uint32_t addr){
    asm volatile("ldmatrix.sync.aligned.m8n8.x4.shared.b16 {%0,%1,%2,%3}, [%4];"
      : "=r"(r[0]),"=r"(r[1]),"=r"(r[2]),"=r"(r[3]) : "r"(addr));
}
__device__ __forceinline__ void ldsm_x2(uint32_t* r, uint32_t addr){
    asm volatile("ldmatrix.sync.aligned.m8n8.x2.shared.b16 {%0,%1}, [%2];"
      : "=r"(r[0]),"=r"(r[1]) : "r"(addr));
}
__device__ __forceinline__ void mma_bf16(float* c, const uint32_t* a, const uint32_t* b){
    asm volatile("mma.sync.aligned.m16n8k16.row.col.f32.bf16.bf16.f32 "
        "{%0,%1,%2,%3}, {%4,%5,%6,%7}, {%8,%9}, {%0,%1,%2,%3};"
        : "+f"(c[0]), "+f"(c[1]), "+f"(c[2]), "+f"(c[3])
        : "r"(a[0]), "r"(a[1]), "r"(a[2]), "r"(a[3]), "r"(b[0]), "r"(b[1]));
}
__device__ __forceinline__ void cp16(uint32_t dst, const void* src){
    asm volatile("cp.async.cg.shared.global [%0], [%1], 16;" :: "r"(dst), "l"(src));
}
#define CP_COMMIT() asm volatile("cp.async.commit_group;" ::: "memory")
#define CP_WAIT1()  asm volatile("cp.async.wait_group 1;" ::: "memory")
#define CP_WAIT0()  asm volatile("cp.async.wait_group 0;" ::: "memory")

// bf16 split helpers
__device__ __forceinline__ void split2(float v, __nv_bfloat16& h, __nv_bfloat16& l){
    h = __float2bfloat16(v);
    l = __float2bfloat16(v - __bfloat162float(h));
}

// ============================ scratch (device globals) ============================
__device__ float g_x  [N_BT*N_D];
__device__ float g_qkv[N_BT*N_QKV];
__device__ __nv_bfloat16 g_hh [N_BT*N_D],  g_hl [N_BT*N_D];    // LN out / attn out (A operand)
__device__ __nv_bfloat16 g_ffh[N_BT*N_DF], g_ffl[N_BT*N_DF];   // GELU out (A operand)

// transposed + split weights: [N, K] row-major bf16 (hi, lo)
__device__ __nv_bfloat16 g_wqkv_h[N_L*N_QKV*N_D], g_wqkv_l[N_L*N_QKV*N_D];
__device__ __nv_bfloat16 g_wo_h  [N_L*N_D*N_D],   g_wo_l  [N_L*N_D*N_D];
__device__ __nv_bfloat16 g_w1_h  [N_L*N_DF*N_D],  g_w1_l  [N_L*N_DF*N_D];
__device__ __nv_bfloat16 g_w2_h  [N_L*N_D*N_DF],  g_w2_l  [N_L*N_D*N_DF];
__device__ __nv_bfloat16 g_hd_h  [(size_t)N_V*N_D], g_hd_l [(size_t)N_V*N_D];

// ============================ weight convert (transpose + bf16 split) ============================
// src W [K, N] f32 -> out [N, K] bf16 hi/lo. 64k x 32n tile, 16B coalesced stores.
__global__ __launch_bounds__(256) void convw_kernel(const float* __restrict__ W,
                                                    __nv_bfloat16* __restrict__ oh,
                                                    __nv_bfloat16* __restrict__ ol,
                                                    int K, int N){
    __shared__ float t[64][33];
    const int n0 = blockIdx.x*32, k0 = blockIdx.y*64;
    const int tx = threadIdx.x & 31, ty = threadIdx.x >> 5;
    #pragma unroll
    for(int r = ty; r < 64; r += 8)
        t[r][tx] = W[(size_t)(k0+r)*N + n0 + tx];
    __syncthreads();
    const int n = threadIdx.x >> 3, k8 = (threadIdx.x & 7)*8;
    ushort hh[8], ll[8];
    #pragma unroll
    for(int j=0;j<8;j++){
        float v = t[k8+j][n];
        __nv_bfloat16 h, l; split2(v, h, l);
        hh[j] = __bfloat16_as_ushort(h);
        ll[j] = __bfloat16_as_ushort(l);
    }
    size_t o = (size_t)(n0+n)*K + k0 + k8;
    *(uint4*)(oh + o) = *(uint4*)hh;
    *(uint4*)(ol + o) = *(uint4*)ll;
}

// ============================ embedding ============================
__global__ __launch_bounds__(256) void embed_kernel(const int* __restrict__ idx,
                                                    const float* __restrict__ tok,
                                                    const float* __restrict__ pos){
    int bt = blockIdx.x;
    int t  = bt & (N_T-1);
    int token = idx[bt];
    const float* tp = tok + (size_t)token*N_D;
    const float* pp = pos + (size_t)t*N_D;
    float* xp = g_x + (size_t)bt*N_D;
    for(int d = threadIdx.x; d < N_D; d += 256)
        xp[d] = tp[d] + pp[d];
}

// ============================ layernorm -> split bf16 ============================
__global__ __launch_bounds__(256) void ln_kernel(const float* __restrict__ in,
                                                 __nv_bfloat16* __restrict__ outh,
                                                 __nv_bfloat16* __restrict__ outl,
                                                 const float* __restrict__ gam,
                                                 const float* __restrict__ bet){
    int row = blockIdx.x;
    int tid = threadIdx.x;
    const float* xr = in + (size_t)row*N_D;
    float v0 = xr[tid], v1 = xr[tid+256], v2 = xr[tid+512];
    __shared__ float red[8];
    float s = v0+v1+v2;
    #pragma unroll
    for(int o=16;o>0;o>>=1) s += __shfl_xor_sync(0xffffffffu, s, o);
    if((tid&31)==0) red[tid>>5] = s;
    __syncthreads();
    float tot = 0.f;
    #pragma unroll
    for(int w=0;w<8;w++) tot += red[w];
    float mu = tot * (1.f/N_D);
    float d0=v0-mu, d1=v1-mu, d2=v2-mu;
    float s2 = d0*d0 + d1*d1 + d2*d2;
    #pragma unroll
    for(int o=16;o>0;o>>=1) s2 += __shfl_xor_sync(0xffffffffu, s2, o);
    __syncthreads();
    if((tid&31)==0) red[tid>>5] = s2;
    __syncthreads();
    float tot2 = 0.f;
    #pragma unroll
    for(int w=0;w<8;w++) tot2 += red[w];
    float rstd = rsqrtf(tot2*(1.f/N_D) + 1e-5f);
    __nv_bfloat16* oh = outh + (size_t)row*N_D;
    __nv_bfloat16* ol = outl + (size_t)row*N_D;
    float y0 = d0*rstd*gam[tid]     + bet[tid];
    float y1 = d1*rstd*gam[tid+256] + bet[tid+256];
    float y2 = d2*rstd*gam[tid+512] + bet[tid+512];
    split2(y0, oh[tid],     ol[tid]);
    split2(y1, oh[tid+256], ol[tid+256]);
    split2(y2, oh[tid+512], ol[tid+512]);
}

// ============================ mma.sync split-bf16 GEMM ============================
// C[M,N] = A[M,K] @ W[K,N]; A given split (Ah,Al [M,K]), W split+transposed (Bh,Bl [N,K]).
// CTA 128x128x32, 8 warps of 64x32, 3-stage cp.async ring, pure ldsm+mma hot loop.
// D = Ah*Bh + Ah*Bl + Al*Bh  (fp32 accumulate).
// EPI: 0 none, 1 +bias, 2 +bias+residual, 3 +bias then exact GELU.
// SPLIT_OUT: write Ch/Cl bf16 pair instead of f32 C.
#define BM 128
#define BN 128
#define BK 32
#define SA 40                      // smem stride in halfs (32 + 8 pad)
#define TILE_B (BM*SA*2)           // 10240
#define OFF_AH 0
#define OFF_AL (1*TILE_B)
#define OFF_BH (2*TILE_B)
#define OFF_BL (3*TILE_B)
#define STAGE_BYTES (4*TILE_B)     // 40960
#define NSTG 3
#define GEMM_SMEM (NSTG*STAGE_BYTES)  // 122880

template<int EPI, int SPLIT_OUT>
__global__ void __launch_bounds__(256) gemm_mma(
        const __nv_bfloat16* __restrict__ Ah, const __nv_bfloat16* __restrict__ Al,
        const __nv_bfloat16* __restrict__ Bh, const __nv_bfloat16* __restrict__ Bl,
        const float* __restrict__ bias, const float* __restrict__ res,
        float* __restrict__ C,
        __nv_bfloat16* __restrict__ Ch, __nv_bfloat16* __restrict__ Cl,
        int M, int N, int K){
    extern __shared__ char sm[];
    const uint32_t sb = smem_u32(sm);
    const int tid = threadIdx.x, wid = tid>>5, lane = tid&31;
    const int mBase = blockIdx.x*BM, nBase = blockIdx.y*BN;
    const int wm = (wid>>2)*64, wn = (wid&3)*32;

    const __nv_bfloat16* Ahp = Ah + (size_t)mBase*K;
    const __nv_bfloat16* Alp = Al + (size_t)mBase*K;
    const __nv_bfloat16* Bhp = Bh + (size_t)nBase*K;
    const __nv_bfloat16* Blp = Bl + (size_t)nBase*K;
    const int nk = K / BK;

    float c[4][4][4];
    #pragma unroll
    for(int mt=0;mt<4;mt++)
        #pragma unroll
        for(int nt=0;nt<4;nt++)
            #pragma unroll
            for(int r=0;r<4;r++) c[mt][nt][r] = 0.f;

    // prefetch: both A (128 rows) and B (128 rows), 4x16B per row per split
    auto prefetch = [&](int k0, int s){
        uint32_t base = sb + s*STAGE_BYTES;
        #pragma unroll
        for(int i=0;i<2;i++){
            int v = tid + i*256;
            int row = v >> 2, seg = (v & 3)*8;
            uint32_t off = (uint32_t)((row*SA + seg)*2);
            cp16(base + OFF_AH + off, Ahp + (size_t)row*K + k0 + seg);
            cp16(base + OFF_AL + off, Alp + (size_t)row*K + k0 + seg);
            cp16(base + OFF_BH + off, Bhp + (size_t)row*K + k0 + seg);
            cp16(base + OFF_BL + off, Blp + (size_t)row*K + k0 + seg);
        }
    };

    auto compute = [&](uint32_t stg){
        #pragma unroll
        for(int ks=0;ks<2;ks++){
            uint32_t ah[4][4], al[4][4], bh[4][2], bl[4][2];
            const uint32_t a_lo = (uint32_t)(((lane&15)*SA + ks*16 + (lane>>4)*8)*2);
            #pragma unroll
            for(int mt=0;mt<4;mt++){
                uint32_t a = stg + (uint32_t)(((wm + mt*16)*SA)*2) + a_lo;
                ldsm_x4(ah[mt], a + OFF_AH);
                ldsm_x4(al[mt], a + OFF_AL);
            }
            const uint32_t b_lo = (uint32_t)(((lane&7)*SA + ks*16 + ((lane>>3)&1)*8)*2);
            #pragma unroll
            for(int nt=0;nt<4;nt++){
                uint32_t b = stg + (uint32_t)(((wn + nt*8)*SA)*2) + b_lo;
                ldsm_x2(bh[nt], b + OFF_BH);
                ldsm_x2(bl[nt], b + OFF_BL);
            }
            #pragma unroll
            for(int mt=0;mt<4;mt++)
                #pragma unroll
                for(int nt=0;nt<4;nt++){
                    mma_bf16(c[mt][nt], ah[mt], bh[nt]);
                    mma_bf16(c[mt][nt], ah[mt], bl[nt]);
                    mma_bf16(c[mt][nt], al[mt], bh[nt]);
                }
        }
    };

    // prologue: stages 0,1 in flight (nk >= 24 always here)
    prefetch(0, 0);    CP_COMMIT();
    prefetch(BK, 1);   CP_COMMIT();

    for(int i=0;i<nk;i++){
        if(i < nk-1) CP_WAIT1(); else CP_WAIT0();
        __syncthreads();
        if(i+2 < nk){ prefetch((i+2)*BK, (i+2)%NSTG); CP_COMMIT(); }
        compute(sb + (i%NSTG)*STAGE_BYTES);
    }

    // ---- epilogue ----
    const int g = lane>>2, t2 = (lane&3)*2;
    #pragma unroll
    for(int mt=0;mt<4;mt++){
        const int row0 = mBase + wm + mt*16 + g;
        #pragma unroll
        for(int nt=0;nt<4;nt++){
            const int col = nBase + wn + nt*8 + t2;
            float v[4] = { c[mt][nt][0], c[mt][nt][1], c[mt][nt][2], c[mt][nt][3] };
            if(EPI != 0){
                float2 b2 = *(const float2*)(bias + col);
                v[0]+=b2.x; v[1]+=b2.y; v[2]+=b2.x; v[3]+=b2.y;
            }
            if(EPI == 2){
                float2 r0 = *(const float2*)(res + (size_t)row0*N + col);
                float2 r1 = *(const float2*)(res + (size_t)(row0+8)*N + col);
                v[0]+=r0.x; v[1]+=r0.y; v[2]+=r1.x; v[3]+=r1.y;
            }
            if(EPI == 3){
                #pragma unroll
                for(int r=0;r<4;r++) v[r] = 0.5f*v[r]*(1.f + erff(v[r]*0.70710678118654752f));
            }
            if(SPLIT_OUT){
                __nv_bfloat16 h0,l0,h1,l1,h2,l2,h3,l3;
                split2(v[0],h0,l0); split2(v[1],h1,l1);
                split2(v[2],h2,l2); split2(v[3],h3,l3);
                ushort2 ph0 = make_ushort2(__bfloat16_as_ushort(h0), __bfloat16_as_ushort(h1));
                ushort2 pl0 = make_ushort2(__bfloat16_as_ushort(l0), __bfloat16_as_ushort(l1));
                ushort2 ph1 = make_ushort2(__bfloat16_as_ushort(h2), __bfloat16_as_ushort(h3));
                ushort2 pl1 = make_ushort2(__bfloat16_as_ushort(l2), __bfloat16_as_ushort(l3));
                *(ushort2*)(Ch + (size_t)row0*N + col)     = ph0;
                *(ushort2*)(Cl + (size_t)row0*N + col)     = pl0;
                *(ushort2*)(Ch + (size_t)(row0+8)*N + col) = ph1;
                *(ushort2*)(Cl + (size_t)(row0+8)*N + col) = pl1;
            } else {
                *(float2*)(C + (size_t)row0*N + col)     = make_float2(v[0], v[1]);
                *(float2*)(C + (size_t)(row0+8)*N + col) = make_float2(v[2], v[3]);
            }
        }
    }
}

// ============================ fused causal flash attention (fp32 SIMT, split-bf16 out) ====
// QKV packed [B*T, 2304]: Q at col h*64, K at 768+h*64, V at 1536+h*64.
#define APAD 65
#define ATT_SMEM (3*64*APAD*4)
#define QKV_S N_QKV

__global__ __launch_bounds__(256) void attn_kernel(const float* __restrict__ QKV,
                                                   __nv_bfloat16* __restrict__ Oh,
                                                   __nv_bfloat16* __restrict__ Ol){
    extern __shared__ float smf[];
    float* Qs  = smf;
    float* KVs = smf + 64*APAD;
    float* Ps  = smf + 2*64*APAD;
    const int qtile = blockIdx.x;
    const int bh = blockIdx.y;
    const int b = bh / N_H, h = bh % N_H;
    const int tid = threadIdx.x;
    const int tr = tid >> 4, tc = tid & 15;
    const float* Qb = QKV + (size_t)b*N_T*QKV_S + h*64;
    const float* Kb = Qb + N_D;
    const float* Vb = Qb + 2*N_D;

    for(int v4 = tid; v4 < 1024; v4 += 256){
        int r = v4 >> 4, c = (v4 & 15) << 2;
        float4 f = *(const float4*)(Qb + (size_t)(qtile*64 + r)*QKV_S + c);
        float* d = Qs + r*APAD + c;
        d[0]=f.x; d[1]=f.y; d[2]=f.z; d[3]=f.w;
    }

    float m_[4], l_[4], acc[4][4];
    #pragma unroll
    for(int i=0;i<4;i++){
        m_[i] = -1e30f; l_[i] = 0.f;
        #pragma unroll
        for(int j=0;j<4;j++) acc[i][j] = 0.f;
    }

    for(int kt = 0; kt <= qtile; kt++){
        for(int v4 = tid; v4 < 1024; v4 += 256){
            int r = v4 >> 4, c = (v4 & 15) << 2;
            float4 f = *(const float4*)(Kb + (size_t)(kt*64 + r)*QKV_S + c);
            float* d = KVs + r*APAD + c;
            d[0]=f.x; d[1]=f.y; d[2]=f.z; d[3]=f.w;
        }
        __syncthreads();

        float s[4][4];
        #pragma unroll
        for(int i=0;i<4;i++)
            #pragma unroll
            for(int j=0;j<4;j++) s[i][j] = 0.f;
        #pragma unroll 8
        for(int kk=0;kk<64;kk++){
            float qa[4], ka[4];
            #pragma unroll
            for(int i=0;i<4;i++) qa[i] = Qs[(tr*4+i)*APAD + kk];
            #pragma unroll
            for(int j=0;j<4;j++) ka[j] = KVs[(tc*4+j)*APAD + kk];
            #pragma unroll
            for(int i=0;i<4;i++)
                #pragma unroll
                for(int j=0;j<4;j++) s[i][j] += qa[i]*ka[j];
        }
        const float scl = 0.125f;
        if(kt == qtile){
            #pragma unroll
            for(int i=0;i<4;i++)
                #pragma unroll
                for(int j=0;j<4;j++)
                    s[i][j] = (tc*4+j <= tr*4+i) ? s[i][j]*scl : -1e30f;
        } else {
            #pragma unroll
            for(int i=0;i<4;i++)
                #pragma unroll
                for(int j=0;j<4;j++) s[i][j] *= scl;
        }

        #pragma unroll
        for(int i=0;i<4;i++){
            float rm = fmaxf(fmaxf(s[i][0],s[i][1]), fmaxf(s[i][2],s[i][3]));
            #pragma unroll
            for(int o=8;o>0;o>>=1) rm = fmaxf(rm, __shfl_xor_sync(0xffffffffu, rm, o));
            float mn = fmaxf(m_[i], rm);
            float corr = expf(m_[i] - mn);
            m_[i] = mn;
            float rs = 0.f;
            #pragma unroll
            for(int j=0;j<4;j++){ float p = expf(s[i][j] - mn); s[i][j] = p; rs += p; }
            #pragma unroll
            for(int o=8;o>0;o>>=1) rs += __shfl_xor_sync(0xffffffffu, rs, o);
            l_[i] = l_[i]*corr + rs;
            #pragma unroll
            for(int j=0;j<4;j++){ acc[i][j] *= corr; Ps[(tr*4+i)*APAD + tc*4+j] = s[i][j]; }
        }
        __syncthreads();

        for(int v4 = tid; v4 < 1024; v4 += 256){
            int r = v4 >> 4, c = (v4 & 15) << 2;
            float4 f = *(const float4*)(Vb + (size_t)(kt*64 + r)*QKV_S + c);
            float* d = KVs + r*APAD + c;
            d[0]=f.x; d[1]=f.y; d[2]=f.z; d[3]=f.w;
        }
        __syncthreads();

        #pragma unroll 8
        for(int kk=0;kk<64;kk++){
            float pa[4], va[4];
            #pragma unroll
            for(int i=0;i<4;i++) pa[i] = Ps[(tr*4+i)*APAD + kk];
            #pragma unroll
            for(int j=0;j<4;j++) va[j] = KVs[kk*APAD + tc*4 + j];
            #pragma unroll
            for(int i=0;i<4;i++)
                #pragma unroll
                for(int j=0;j<4;j++) acc[i][j] += pa[i]*va[j];
        }
        __syncthreads();
    }

    __nv_bfloat16* Obh = Oh + (size_t)b*N_T*N_D + h*64;
    __nv_bfloat16* Obl = Ol + (size_t)b*N_T*N_D + h*64;
    #pragma unroll
    for(int i=0;i<4;i++){
        float inv = 1.f / l_[i];
        int r = qtile*64 + tr*4 + i;
        ushort hh[4], ll[4];
        #pragma unroll
        for(int j=0;j<4;j++){
            __nv_bfloat16 h_, l_2; split2(acc[i][j]*inv, h_, l_2);
            hh[j] = __bfloat16_as_ushort(h_); ll[j] = __bfloat16_as_ushort(l_2);
        }
        *(ushort4*)(Obh + (size_t)r*N_D + tc*4) = *(ushort4*)hh;
        *(ushort4*)(Obl + (size_t)r*N_D + tc*4) = *(ushort4*)ll;
    }
}

// ============================ host orchestration ============================
extern "C" void kernel_launch(void* const* d_in, const int* in_sizes, int n_in,
                              void* d_out, int out_size){
    const int*   idx   = (const int*)  d_in[0];
    const float* tok   = (const float*)d_in[1];
    const float* pos   = (const float*)d_in[2];
    const float* Wq    = (const float*)d_in[3];
    const float* Wk    = (const float*)d_in[4];
    const float* Wv    = (const float*)d_in[5];
    const float* Wo    = (const float*)d_in[6];
    const float* bo    = (const float*)d_in[7];
    const float* W1    = (const float*)d_in[8];
    const float* b1    = (const float*)d_in[9];
    const float* W2    = (const float*)d_in[10];
    const float* b2    = (const float*)d_in[11];
    const float* ln1g  = (const float*)d_in[12];
    const float* ln1b  = (const float*)d_in[13];
    const float* ln2g  = (const float*)d_in[14];
    const float* ln2b  = (const float*)d_in[15];
    const float* lnfg  = (const float*)d_in[16];
    const float* lnfb  = (const float*)d_in[17];
    const float* headW = (const float*)d_in[18];
    const float* headb = (const float*)d_in[19];
    float* out = (float*)d_out;

    float *x,*qkv;
    cudaGetSymbolAddress((void**)&x,   g_x);
    cudaGetSymbolAddress((void**)&qkv, g_qkv);
    __nv_bfloat16 *hh,*hl,*ffh,*ffl;
    cudaGetSymbolAddress((void**)&hh,  g_hh);
    cudaGetSymbolAddress((void**)&hl,  g_hl);
    cudaGetSymbolAddress((void**)&ffh, g_ffh);
    cudaGetSymbolAddress((void**)&ffl, g_ffl);
    __nv_bfloat16 *wqkvh,*wqkvl,*woh,*wol,*w1h,*w1l,*w2h,*w2l,*hdh,*hdl;
    cudaGetSymbolAddress((void**)&wqkvh, g_wqkv_h);
    cudaGetSymbolAddress((void**)&wqkvl, g_wqkv_l);
    cudaGetSymbolAddress((void**)&woh,   g_wo_h);
    cudaGetSymbolAddress((void**)&wol,   g_wo_l);
    cudaGetSymbolAddress((void**)&w1h,   g_w1_h);
    cudaGetSymbolAddress((void**)&w1l,   g_w1_l);
    cudaGetSymbolAddress((void**)&w2h,   g_w2_h);
    cudaGetSymbolAddress((void**)&w2l,   g_w2_l);
    cudaGetSymbolAddress((void**)&hdh,   g_hd_h);
    cudaGetSymbolAddress((void**)&hdl,   g_hd_l);

    cudaFuncSetAttribute(attn_kernel, cudaFuncAttributeMaxDynamicSharedMemorySize, ATT_SMEM);
    cudaFuncSetAttribute(gemm_mma<0,0>, cudaFuncAttributeMaxDynamicSharedMemorySize, GEMM_SMEM);
    cudaFuncSetAttribute(gemm_mma<1,0>, cudaFuncAttributeMaxDynamicSharedMemorySize, GEMM_SMEM);
    cudaFuncSetAttribute(gemm_mma<2,0>, cudaFuncAttributeMaxDynamicSharedMemorySize, GEMM_SMEM);
    cudaFuncSetAttribute(gemm_mma<3,1>, cudaFuncAttributeMaxDynamicSharedMemorySize, GEMM_SMEM);

    // ---- weight conversion: transpose to [N,K] + bf16 hi/lo split ----
    // convw grid: (N/32, K/64)
    const dim3 cDD(N_D/32,  N_D/64);    // 24 x 12
    const dim3 cW1(N_DF/32, N_D/64);    // out [3072,768]
    const dim3 cW2(N_D/32,  N_DF/64);   // out [768,3072]
    for(int l=0;l<N_L;l++){
        size_t qkvOff = (size_t)l*N_QKV*N_D;
        convw_kernel<<<cDD,256>>>(Wq + (size_t)l*N_D*N_D, wqkvh + qkvOff,                     wqkvl + qkvOff,                     N_D, N_D);
        convw_kernel<<<cDD,256>>>(Wk + (size_t)l*N_D*N_D, wqkvh + qkvOff + (size_t)N_D*N_D,   wqkvl + qkvOff + (size_t)N_D*N_D,   N_D, N_D);
        convw_kernel<<<cDD,256>>>(Wv + (size_t)l*N_D*N_D, wqkvh + qkvOff + (size_t)2*N_D*N_D, wqkvl + qkvOff + (size_t)2*N_D*N_D, N_D, N_D);
        convw_kernel<<<cDD,256>>>(Wo + (size_t)l*N_D*N_D, woh + (size_t)l*N_D*N_D, wol + (size_t)l*N_D*N_D, N_D, N_D);
        convw_kernel<<<cW1,256>>>(W1 + (size_t)l*N_D*N_DF, w1h + (size_t)l*N_DF*N_D, w1l + (size_t)l*N_DF*N_D, N_D, N_DF);
        convw_kernel<<<cW2,256>>>(W2 + (size_t)l*N_DF*N_D, w2h + (size_t)l*N_D*N_DF, w2l + (size_t)l*N_D*N_DF, N_DF, N_D);
    }
    convw_kernel<<<dim3(N_V/32, N_D/64),256>>>(headW, hdh, hdl, N_D, N_V);

    embed_kernel<<<N_BT, 256>>>(idx, tok, pos);

    const dim3 gQKV(N_BT/BM, N_QKV/BN);  // 32 x 18
    const dim3 gOUT(N_BT/BM, N_D/BN);    // 32 x 6
    const dim3 gFF1(N_BT/BM, N_DF/BN);   // 32 x 24
    const dim3 gHead(N_BT/BM, N_V/BN);   // 32 x 250
    const dim3 gAtt(N_T/64, N_Bc*N_H);   // 16 x 48

    for(int l=0;l<N_L;l++){
        ln_kernel<<<N_BT,256>>>(x, hh, hl, ln1g + l*N_D, ln1b + l*N_D);
        gemm_mma<0,0><<<gQKV,256,GEMM_SMEM>>>(hh, hl,
                wqkvh + (size_t)l*N_QKV*N_D, wqkvl + (size_t)l*N_QKV*N_D,
                nullptr, nullptr, qkv, nullptr, nullptr, N_BT, N_QKV, N_D);
        attn_kernel<<<gAtt,256,ATT_SMEM>>>(qkv, hh, hl);
        gemm_mma<2,0><<<gOUT,256,GEMM_SMEM>>>(hh, hl,
                woh + (size_t)l*N_D*N_D, wol + (size_t)l*N_D*N_D,
                bo + l*N_D, x, x, nullptr, nullptr, N_BT, N_D, N_D);
        ln_kernel<<<N_BT,256>>>(x, hh, hl, ln2g + l*N_D, ln2b + l*N_D);
        gemm_mma<3,1><<<gFF1,256,GEMM_SMEM>>>(hh, hl,
                w1h + (size_t)l*N_DF*N_D, w1l + (size_t)l*N_DF*N_D,
                b1 + l*N_DF, nullptr, nullptr, ffh, ffl, N_BT, N_DF, N_D);
        gemm_mma<2,0><<<gOUT,256,GEMM_SMEM>>>(ffh, ffl,
                w2h + (size_t)l*N_D*N_DF, w2l + (size_t)l*N_D*N_DF,
                b2 + l*N_D, x, x, nullptr, nullptr, N_BT, N_D, N_DF);
    }
    ln_kernel<<<N_BT,256>>>(x, hh, hl, lnfg, lnfb);
    gemm_mma<1,0><<<gHead,256,GEMM_SMEM>>>(hh, hl, hdh, hdl,
            headb, nullptr, out, nullptr, nullptr, N_BT, N_V, N_D);
}

// round 11
// speedup vs baseline: 1.8572x; 1.8557x over previous
#include <cuda_runtime.h>
#include <cuda_fp16.h>
#include <math.h>
#include <stdint.h>

#define N_Bc  4
#define N_T   1024
#define N_D   768
#define N_H   12
#define N_L   6
#define N_DF  3072
#define N_V   32000
#define N_BT  (N_Bc*N_T)
#define N_QKV (3*N_D)

// ============================ PTX helpers ============================
__device__ __forceinline__ uint32_t smem_u32(const void* p){
    uint32_t a;
    asm("{ .reg .u64 t; cvta.to.shared.u64 t, %1; cvt.u32.u64 %0, t; }" : "=r"(a) : "l"(p));
    return a;
}
__device__ __forceinline__ void ldsm_x4(uint32_t* r, uint32_t addr){
    asm volatile("ldmatrix.sync.aligned.m8n8.x4.shared.b16 {%0,%1,%2,%3}, [%4];"
      : "=r"(r[0]),"=r"(r[1]),"=r"(r[2]),"=r"(r[3]) : "r"(addr));
}
__device__ __forceinline__ void ldsm_x2(uint32_t* r, uint32_t addr){
    asm volatile("ldmatrix.sync.aligned.m8n8.x2.shared.b16 {%0,%1}, [%2];"
      : "=r"(r[0]),"=r"(r[1]) : "r"(addr));
}
__device__ __forceinline__ void mma_f16(float* c, const uint32_t* a, const uint32_t* b){
    asm volatile("mma.sync.aligned.m16n8k16.row.col.f32.f16.f16.f32 "
        "{%0,%1,%2,%3}, {%4,%5,%6,%7}, {%8,%9}, {%0,%1,%2,%3};"
        : "+f"(c[0]), "+f"(c[1]), "+f"(c[2]), "+f"(c[3])
        : "r"(a[0]), "r"(a[1]), "r"(a[2]), "r"(a[3]), "r"(b[0]), "r"(b[1]));
}
__device__ __forceinline__ void cp16(uint32_t dst, const void* src){
    asm volatile("cp.async.cg.shared.global [%0], [%1], 16;" :: "r"(dst), "l"(src));
}
#define CP_COMMIT() asm volatile("cp.async.commit_group;" ::: "memory")
#define CP_WAIT2()  asm volatile("cp.async.wait_group 2;" ::: "memory")
#define CP_WAIT1()  asm volatile("cp.async.wait_group 1;" ::: "memory")
#define CP_WAIT0()  asm volatile("cp.async.wait_group 0;" ::: "memory")

// ============================ scratch (device globals) ============================
__device__ float g_x  [N_BT*N_D];
__device__ float g_qkv[N_BT*N_QKV];
__device__ __half g_a  [N_BT*N_D];     // LN out / attn out (A operand, fp16)
__device__ __half g_aff[N_BT*N_DF];    // GELU out (A operand, fp16)

// transposed weights: [N, K] row-major fp16
__device__ __half g_wqkv[N_L*N_QKV*N_D];
__device__ __half g_wo  [N_L*N_D*N_D];
__device__ __half g_w1  [N_L*N_DF*N_D];
__device__ __half g_w2  [N_L*N_D*N_DF];
__device__ __half g_hd  [(size_t)N_V*N_D];

// ============================ weight convert (transpose -> fp16 [N,K]) ============================
__global__ __launch_bounds__(256) void convw_kernel(const float* __restrict__ W,
                                                    __half* __restrict__ o,
                                                    int K, int N){
    __shared__ float t[64][33];
    const int n0 = blockIdx.x*32, k0 = blockIdx.y*64;
    const int tx = threadIdx.x & 31, ty = threadIdx.x >> 5;
    #pragma unroll
    for(int r = ty; r < 64; r += 8)
        t[r][tx] = W[(size_t)(k0+r)*N + n0 + tx];
    __syncthreads();
    const int n = threadIdx.x >> 3, k8 = (threadIdx.x & 7)*8;
    ushort hh[8];
    #pragma unroll
    for(int j=0;j<8;j++)
        hh[j] = __half_as_ushort(__float2half(t[k8+j][n]));
    *(uint4*)(o + (size_t)(n0+n)*K + k0 + k8) = *(uint4*)hh;
}

// ============================ embedding ============================
__global__ __launch_bounds__(256) void embed_kernel(const int* __restrict__ idx,
                                                    const float* __restrict__ tok,
                                                    const float* __restrict__ pos){
    int bt = blockIdx.x;
    int t  = bt & (N_T-1);
    int token = idx[bt];
    const float* tp = tok + (size_t)token*N_D;
    const float* pp = pos + (size_t)t*N_D;
    float* xp = g_x + (size_t)bt*N_D;
    for(int d = threadIdx.x; d < N_D; d += 256)
        xp[d] = tp[d] + pp[d];
}

// ============================ layernorm -> fp16 ============================
__global__ __launch_bounds__(256) void ln_kernel(const float* __restrict__ in,
                                                 __half* __restrict__ outv,
                                                 const float* __restrict__ gam,
                                                 const float* __restrict__ bet){
    int row = blockIdx.x;
    int tid = threadIdx.x;
    const float* xr = in + (size_t)row*N_D;
    float v0 = xr[tid], v1 = xr[tid+256], v2 = xr[tid+512];
    __shared__ float red[8];
    float s = v0+v1+v2;
    #pragma unroll
    for(int o=16;o>0;o>>=1) s += __shfl_xor_sync(0xffffffffu, s, o);
    if((tid&31)==0) red[tid>>5] = s;
    __syncthreads();
    float tot = 0.f;
    #pragma unroll
    for(int w=0;w<8;w++) tot += red[w];
    float mu = tot * (1.f/N_D);
    float d0=v0-mu, d1=v1-mu, d2=v2-mu;
    float s2 = d0*d0 + d1*d1 + d2*d2;
    #pragma unroll
    for(int o=16;o>0;o>>=1) s2 += __shfl_xor_sync(0xffffffffu, s2, o);
    __syncthreads();
    if((tid&31)==0) red[tid>>5] = s2;
    __syncthreads();
    float tot2 = 0.f;
    #pragma unroll
    for(int w=0;w<8;w++) tot2 += red[w];
    float rstd = rsqrtf(tot2*(1.f/N_D) + 1e-5f);
    __half* orow = outv + (size_t)row*N_D;
    orow[tid]     = __float2half(d0*rstd*gam[tid]     + bet[tid]);
    orow[tid+256] = __float2half(d1*rstd*gam[tid+256] + bet[tid+256]);
    orow[tid+512] = __float2half(d2*rstd*gam[tid+512] + bet[tid+512]);
}

// ============================ fp16 mma.sync GEMM ============================
// C[M,N] = A[M,K] @ W[K,N]; A fp16 [M,K], W fp16 transposed [N,K].
// CTA 128x128x32, 8 warps of 64x32, 4-stage cp.async ring.
// EPI: 0 none, 1 +bias, 2 +bias+residual, 3 +bias then exact GELU.
// HOUT: write fp16 C instead of f32.
#define BM 128
#define BN 128
#define BK 32
#define SA 40                      // smem stride in halfs (32 + 8 pad)
#define TILE_B (BM*SA*2)           // 10240
#define OFF_A 0
#define OFF_B TILE_B
#define STAGE_BYTES (2*TILE_B)     // 20480
#define NSTG 4
#define GEMM_SMEM (NSTG*STAGE_BYTES)  // 81920

template<int EPI, int HOUT>
__global__ void __launch_bounds__(256,2) gemm_mma(
        const __half* __restrict__ A,
        const __half* __restrict__ B,
        const float* __restrict__ bias, const float* __restrict__ res,
        float* __restrict__ C, __half* __restrict__ Chf,
        int M, int N, int K){
    extern __shared__ char sm[];
    const uint32_t sb = smem_u32(sm);
    const int tid = threadIdx.x, wid = tid>>5, lane = tid&31;
    const int mBase = blockIdx.x*BM, nBase = blockIdx.y*BN;
    const int wm = (wid>>2)*64, wn = (wid&3)*32;

    const __half* Apt = A + (size_t)mBase*K;
    const __half* Bpt = B + (size_t)nBase*K;
    const int nk = K / BK;

    float c[4][4][4];
    #pragma unroll
    for(int mt=0;mt<4;mt++)
        #pragma unroll
        for(int nt=0;nt<4;nt++)
            #pragma unroll
            for(int r=0;r<4;r++) c[mt][nt][r] = 0.f;

    // prefetch: A 128 rows + B 128 rows, 4x16B segs per row; 4 cp16 per thread
    auto prefetch = [&](int k0, int s){
        uint32_t base = sb + s*STAGE_BYTES;
        #pragma unroll
        for(int i=0;i<2;i++){
            int v = tid + i*256;
            int row = v >> 2, seg = (v & 3)*8;
            uint32_t off = (uint32_t)((row*SA + seg)*2);
            cp16(base + OFF_A + off, Apt + (size_t)row*K + k0 + seg);
            cp16(base + OFF_B + off, Bpt + (size_t)row*K + k0 + seg);
        }
    };

    auto compute = [&](uint32_t stg){
        #pragma unroll
        for(int ks=0;ks<2;ks++){
            uint32_t a[4][4], b[4][2];
            const uint32_t a_lo = (uint32_t)(((lane&15)*SA + ks*16 + (lane>>4)*8)*2);
            #pragma unroll
            for(int mt=0;mt<4;mt++)
                ldsm_x4(a[mt], stg + OFF_A + (uint32_t)(((wm + mt*16)*SA)*2) + a_lo);
            const uint32_t b_lo = (uint32_t)(((lane&7)*SA + ks*16 + ((lane>>3)&1)*8)*2);
            #pragma unroll
            for(int nt=0;nt<4;nt++)
                ldsm_x2(b[nt], stg + OFF_B + (uint32_t)(((wn + nt*8)*SA)*2) + b_lo);
            #pragma unroll
            for(int mt=0;mt<4;mt++)
                #pragma unroll
                for(int nt=0;nt<4;nt++)
                    mma_f16(c[mt][nt], a[mt], b[nt]);
        }
    };

    // prologue: 3 stages in flight (nk >= 24 here)
    prefetch(0,    0); CP_COMMIT();
    prefetch(BK,   1); CP_COMMIT();
    prefetch(2*BK, 2); CP_COMMIT();

    for(int i=0;i<nk;i++){
        const int rem = nk-1-i;
        if(rem >= 2)      { CP_WAIT2(); }
        else if(rem == 1) { CP_WAIT1(); }
        else              { CP_WAIT0(); }
        __syncthreads();
        if(i+3 < nk){ prefetch((i+3)*BK, (i+3)&3); CP_COMMIT(); }
        compute(sb + (i&3)*STAGE_BYTES);
    }

    // ---- epilogue ----
    const int g = lane>>2, t2 = (lane&3)*2;
    #pragma unroll
    for(int mt=0;mt<4;mt++){
        const int row0 = mBase + wm + mt*16 + g;
        #pragma unroll
        for(int nt=0;nt<4;nt++){
            const int col = nBase + wn + nt*8 + t2;
            float v[4] = { c[mt][nt][0], c[mt][nt][1], c[mt][nt][2], c[mt][nt][3] };
            if(EPI != 0){
                float2 b2 = *(const float2*)(bias + col);
                v[0]+=b2.x; v[1]+=b2.y; v[2]+=b2.x; v[3]+=b2.y;
            }
            if(EPI == 2){
                float2 r0 = *(const float2*)(res + (size_t)row0*N + col);
                float2 r1 = *(const float2*)(res + (size_t)(row0+8)*N + col);
                v[0]+=r0.x; v[1]+=r0.y; v[2]+=r1.x; v[3]+=r1.y;
            }
            if(EPI == 3){
                #pragma unroll
                for(int r=0;r<4;r++) v[r] = 0.5f*v[r]*(1.f + erff(v[r]*0.70710678118654752f));
            }
            if(HOUT){
                ushort2 p0 = make_ushort2(__half_as_ushort(__float2half(v[0])),
                                          __half_as_ushort(__float2half(v[1])));
                ushort2 p1 = make_ushort2(__half_as_ushort(__float2half(v[2])),
                                          __half_as_ushort(__float2half(v[3])));
                *(ushort2*)(Chf + (size_t)row0*N + col)     = p0;
                *(ushort2*)(Chf + (size_t)(row0+8)*N + col) = p1;
            } else {
                *(float2*)(C + (size_t)row0*N + col)     = make_float2(v[0], v[1]);
                *(float2*)(C + (size_t)(row0+8)*N + col) = make_float2(v[2], v[3]);
            }
        }
    }
}

// ============================ fused causal flash attention (fp32 SIMT, fp16 out) ====
// QKV packed [B*T, 2304]: Q at col h*64, K at 768+h*64, V at 1536+h*64.
#define APAD 65
#define ATT_SMEM (3*64*APAD*4)
#define QKV_S N_QKV

__global__ __launch_bounds__(256) void attn_kernel(const float* __restrict__ QKV,
                                                   __half* __restrict__ O){
    extern __shared__ float smf[];
    float* Qs  = smf;
    float* KVs = smf + 64*APAD;
    float* Ps  = smf + 2*64*APAD;
    const int qtile = blockIdx.x;
    const int bh = blockIdx.y;
    const int b = bh / N_H, h = bh % N_H;
    const int tid = threadIdx.x;
    const int tr = tid >> 4, tc = tid & 15;
    const float* Qb = QKV + (size_t)b*N_T*QKV_S + h*64;
    const float* Kb = Qb + N_D;
    const float* Vb = Qb + 2*N_D;

    for(int v4 = tid; v4 < 1024; v4 += 256){
        int r = v4 >> 4, c = (v4 & 15) << 2;
        float4 f = *(const float4*)(Qb + (size_t)(qtile*64 + r)*QKV_S + c);
        float* d = Qs + r*APAD + c;
        d[0]=f.x; d[1]=f.y; d[2]=f.z; d[3]=f.w;
    }

    float m_[4], l_[4], acc[4][4];
    #pragma unroll
    for(int i=0;i<4;i++){
        m_[i] = -1e30f; l_[i] = 0.f;
        #pragma unroll
        for(int j=0;j<4;j++) acc[i][j] = 0.f;
    }

    for(int kt = 0; kt <= qtile; kt++){
        for(int v4 = tid; v4 < 1024; v4 += 256){
            int r = v4 >> 4, c = (v4 & 15) << 2;
            float4 f = *(const float4*)(Kb + (size_t)(kt*64 + r)*QKV_S + c);
            float* d = KVs + r*APAD + c;
            d[0]=f.x; d[1]=f.y; d[2]=f.z; d[3]=f.w;
        }
        __syncthreads();

        float s[4][4];
        #pragma unroll
        for(int i=0;i<4;i++)
            #pragma unroll
            for(int j=0;j<4;j++) s[i][j] = 0.f;
        #pragma unroll 8
        for(int kk=0;kk<64;kk++){
            float qa[4], ka[4];
            #pragma unroll
            for(int i=0;i<4;i++) qa[i] = Qs[(tr*4+i)*APAD + kk];
            #pragma unroll
            for(int j=0;j<4;j++) ka[j] = KVs[(tc*4+j)*APAD + kk];
            #pragma unroll
            for(int i=0;i<4;i++)
                #pragma unroll
                for(int j=0;j<4;j++) s[i][j] += qa[i]*ka[j];
        }
        const float scl = 0.125f;
        if(kt == qtile){
            #pragma unroll
            for(int i=0;i<4;i++)
                #pragma unroll
                for(int j=0;j<4;j++)
                    s[i][j] = (tc*4+j <= tr*4+i) ? s[i][j]*scl : -1e30f;
        } else {
            #pragma unroll
            for(int i=0;i<4;i++)
                #pragma unroll
                for(int j=0;j<4;j++) s[i][j] *= scl;
        }

        #pragma unroll
        for(int i=0;i<4;i++){
            float rm = fmaxf(fmaxf(s[i][0],s[i][1]), fmaxf(s[i][2],s[i][3]));
            #pragma unroll
            for(int o=8;o>0;o>>=1) rm = fmaxf(rm, __shfl_xor_sync(0xffffffffu, rm, o));
            float mn = fmaxf(m_[i], rm);
            float corr = expf(m_[i] - mn);
            m_[i] = mn;
            float rs = 0.f;
            #pragma unroll
            for(int j=0;j<4;j++){ float p = expf(s[i][j] - mn); s[i][j] = p; rs += p; }
            #pragma unroll
            for(int o=8;o>0;o>>=1) rs += __shfl_xor_sync(0xffffffffu, rs, o);
            l_[i] = l_[i]*corr + rs;
            #pragma unroll
            for(int j=0;j<4;j++){ acc[i][j] *= corr; Ps[(tr*4+i)*APAD + tc*4+j] = s[i][j]; }
        }
        __syncthreads();

        for(int v4 = tid; v4 < 1024; v4 += 256){
            int r = v4 >> 4, c = (v4 & 15) << 2;
            float4 f = *(const float4*)(Vb + (size_t)(kt*64 + r)*QKV_S + c);
            float* d = KVs + r*APAD + c;
            d[0]=f.x; d[1]=f.y; d[2]=f.z; d[3]=f.w;
        }
        __syncthreads();

        #pragma unroll 8
        for(int kk=0;kk<64;kk++){
            float pa[4], va[4];
            #pragma unroll
            for(int i=0;i<4;i++) pa[i] = Ps[(tr*4+i)*APAD + kk];
            #pragma unroll
            for(int j=0;j<4;j++) va[j] = KVs[kk*APAD + tc*4 + j];
            #pragma unroll
            for(int i=0;i<4;i++)
                #pragma unroll
                for(int j=0;j<4;j++) acc[i][j] += pa[i]*va[j];
        }
        __syncthreads();
    }

    __half* Ob = O + (size_t)b*N_T*N_D + h*64;
    #pragma unroll
    for(int i=0;i<4;i++){
        float inv = 1.f / l_[i];
        int r = qtile*64 + tr*4 + i;
        ushort hh[4];
        #pragma unroll
        for(int j=0;j<4;j++)
            hh[j] = __half_as_ushort(__float2half(acc[i][j]*inv));
        *(ushort4*)(Ob + (size_t)r*N_D + tc*4) = *(ushort4*)hh;
    }
}

// ============================ host orchestration ============================
extern "C" void kernel_launch(void* const* d_in, const int* in_sizes, int n_in,
                              void* d_out, int out_size){
    const int*   idx   = (const int*)  d_in[0];
    const float* tok   = (const float*)d_in[1];
    const float* pos   = (const float*)d_in[2];
    const float* Wq    = (const float*)d_in[3];
    const float* Wk    = (const float*)d_in[4];
    const float* Wv    = (const float*)d_in[5];
    const float* Wo    = (const float*)d_in[6];
    const float* bo    = (const float*)d_in[7];
    const float* W1    = (const float*)d_in[8];
    const float* b1    = (const float*)d_in[9];
    const float* W2    = (const float*)d_in[10];
    const float* b2    = (const float*)d_in[11];
    const float* ln1g  = (const float*)d_in[12];
    const float* ln1b  = (const float*)d_in[13];
    const float* ln2g  = (const float*)d_in[14];
    const float* ln2b  = (const float*)d_in[15];
    const float* lnfg  = (const float*)d_in[16];
    const float* lnfb  = (const float*)d_in[17];
    const float* headW = (const float*)d_in[18];
    const float* headb = (const float*)d_in[19];
    float* out = (float*)d_out;

    float *x,*qkv;
    cudaGetSymbolAddress((void**)&x,   g_x);
    cudaGetSymbolAddress((void**)&qkv, g_qkv);
    __half *ah,*aff;
    cudaGetSymbolAddress((void**)&ah,  g_a);
    cudaGetSymbolAddress((void**)&aff, g_aff);
    __half *wqkv,*wo,*w1,*w2,*hd;
    cudaGetSymbolAddress((void**)&wqkv, g_wqkv);
    cudaGetSymbolAddress((void**)&wo,   g_wo);
    cudaGetSymbolAddress((void**)&w1,   g_w1);
    cudaGetSymbolAddress((void**)&w2,   g_w2);
    cudaGetSymbolAddress((void**)&hd,   g_hd);

    cudaFuncSetAttribute(attn_kernel, cudaFuncAttributeMaxDynamicSharedMemorySize, ATT_SMEM);
    cudaFuncSetAttribute(gemm_mma<0,0>, cudaFuncAttributeMaxDynamicSharedMemorySize, GEMM_SMEM);
    cudaFuncSetAttribute(gemm_mma<1,0>, cudaFuncAttributeMaxDynamicSharedMemorySize, GEMM_SMEM);
    cudaFuncSetAttribute(gemm_mma<2,0>, cudaFuncAttributeMaxDynamicSharedMemorySize, GEMM_SMEM);
    cudaFuncSetAttribute(gemm_mma<3,1>, cudaFuncAttributeMaxDynamicSharedMemorySize, GEMM_SMEM);

    // ---- weight conversion: transpose to [N,K] fp16 ----
    const dim3 cDD(N_D/32,  N_D/64);
    const dim3 cW1(N_DF/32, N_D/64);
    const dim3 cW2(N_D/32,  N_DF/64);
    for(int l=0;l<N_L;l++){
        size_t qkvOff = (size_t)l*N_QKV*N_D;
        convw_kernel<<<cDD,256>>>(Wq + (size_t)l*N_D*N_D, wqkv + qkvOff,                     N_D, N_D);
        convw_kernel<<<cDD,256>>>(Wk + (size_t)l*N_D*N_D, wqkv + qkvOff + (size_t)N_D*N_D,   N_D, N_D);
        convw_kernel<<<cDD,256>>>(Wv + (size_t)l*N_D*N_D, wqkv + qkvOff + (size_t)2*N_D*N_D, N_D, N_D);
        convw_kernel<<<cDD,256>>>(Wo + (size_t)l*N_D*N_D, wo + (size_t)l*N_D*N_D, N_D, N_D);
        convw_kernel<<<cW1,256>>>(W1 + (size_t)l*N_D*N_DF, w1 + (size_t)l*N_DF*N_D, N_D, N_DF);
        convw_kernel<<<cW2,256>>>(W2 + (size_t)l*N_DF*N_D, w2 + (size_t)l*N_D*N_DF, N_DF, N_D);
    }
    convw_kernel<<<dim3(N_V/32, N_D/64),256>>>(headW, hd, N_D, N_V);

    embed_kernel<<<N_BT, 256>>>(idx, tok, pos);

    const dim3 gQKV(N_BT/BM, N_QKV/BN);  // 32 x 18
    const dim3 gOUT(N_BT/BM, N_D/BN);    // 32 x 6
    const dim3 gFF1(N_BT/BM, N_DF/BN);   // 32 x 24
    const dim3 gHead(N_BT/BM, N_V/BN);   // 32 x 250
    const dim3 gAtt(N_T/64, N_Bc*N_H);   // 16 x 48

    for(int l=0;l<N_L;l++){
        ln_kernel<<<N_BT,256>>>(x, ah, ln1g + l*N_D, ln1b + l*N_D);
        gemm_mma<0,0><<<gQKV,256,GEMM_SMEM>>>(ah, wqkv + (size_t)l*N_QKV*N_D,
                nullptr, nullptr, qkv, nullptr, N_BT, N_QKV, N_D);
        attn_kernel<<<gAtt,256,ATT_SMEM>>>(qkv, ah);
        gemm_mma<2,0><<<gOUT,256,GEMM_SMEM>>>(ah, wo + (size_t)l*N_D*N_D,
                bo + l*N_D, x, x, nullptr, N_BT, N_D, N_D);
        ln_kernel<<<N_BT,256>>>(x, ah, ln2g + l*N_D, ln2b + l*N_D);
        gemm_mma<3,1><<<gFF1,256,GEMM_SMEM>>>(ah, w1 + (size_t)l*N_DF*N_D,
                b1 + l*N_DF, nullptr, nullptr, aff, N_BT, N_DF, N_D);
        gemm_mma<2,0><<<gOUT,256,GEMM_SMEM>>>(aff, w2 + (size_t)l*N_D*N_DF,
                b2 + l*N_D, x, x, nullptr, N_BT, N_D, N_DF);
    }
    ln_kernel<<<N_BT,256>>>(x, ah, lnfg, lnfb);
    gemm_mma<1,0><<<gHead,256,GEMM_SMEM>>>(ah, hd,
            headb, nullptr, out, nullptr, N_BT, N_V, N_D);
}